// round 1
// baseline (speedup 1.0000x reference)
#include <cuda_runtime.h>
#include <cuda_bf16.h>
#include <math.h>

// GPT forward: B=4, T=512, L=12, C=1024, H=16, HD=64, F=4096, V=32000
#define Bn   4
#define Tn   512
#define Ln   12
#define Cn   1024
#define Hn   16
#define HDn  64
#define Fn   4096
#define Vn   32000
#define BT   (Bn * Tn)          // 2048

// ---------------- static scratch (no allocations allowed) ----------------
__device__ float g_x [BT * Cn];
__device__ float g_xn[BT * Cn];
__device__ float g_q [BT * Cn];
__device__ float g_k [BT * Cn];
__device__ float g_v [BT * Cn];
__device__ float g_y [BT * Cn];
__device__ float g_h [BT * Fn];

// ---------------- embedding ----------------
__global__ void embed_kernel(const int* __restrict__ idx,
                             const float* __restrict__ tok,
                             const float* __restrict__ pos,
                             float* __restrict__ x) {
    int row = blockIdx.x;              // 0..BT-1
    int t = row & (Tn - 1);
    int token = idx[row];
    const float* tp = tok + (size_t)token * Cn;
    const float* pp = pos + (size_t)t * Cn;
    float* xp = x + (size_t)row * Cn;
    for (int c = threadIdx.x; c < Cn; c += 256)
        xp[c] = tp[c] + pp[c];
}

// ---------------- layernorm (one block per row, C=1024) ----------------
__global__ void ln_kernel(const float* __restrict__ in,
                          const float* __restrict__ g,
                          const float* __restrict__ b,
                          float* __restrict__ out) {
    int row = blockIdx.x;
    int tid = threadIdx.x;
    const float* p = in + (size_t)row * Cn;
    float s = 0.f, sq = 0.f;
    for (int c = tid; c < Cn; c += 256) { float v = p[c]; s += v; sq += v * v; }
    __shared__ float rs[256], rq[256];
    rs[tid] = s; rq[tid] = sq; __syncthreads();
    for (int o = 128; o > 0; o >>= 1) {
        if (tid < o) { rs[tid] += rs[tid + o]; rq[tid] += rq[tid + o]; }
        __syncthreads();
    }
    float mean = rs[0] * (1.f / Cn);
    float var  = rq[0] * (1.f / Cn) - mean * mean;
    float inv  = rsqrtf(var + 1e-5f);
    float* op = out + (size_t)row * Cn;
    for (int c = tid; c < Cn; c += 256)
        op[c] = (p[c] - mean) * inv * g[c] + b[c];
}

// ---------------- SGEMM: C[M,N] = A[M,K] @ B[K,N] (+bias)(+relu)(+res) ----
// 64x64 tile, BK=16, 256 threads, 4x4 per-thread microtile.
// All dims are exact multiples of the tile (M=2048; N in {1024,4096,32000};
// K in {1024,4096}) so no bounds checks.
template<bool RELU>
__global__ __launch_bounds__(256)
void gemm64(const float* __restrict__ A, const float* __restrict__ Bm,
            const float* __restrict__ bias, const float* __restrict__ res,
            float* __restrict__ C, int M, int N, int K) {
    __shared__ float As[16][64];
    __shared__ float Bs[16][64];
    const int tid = threadIdx.x;
    const int tx = tid & 15, ty = tid >> 4;
    const int bm = blockIdx.y * 64;
    const int bn = blockIdx.x * 64;

    const int arow = tid >> 2;           // 0..63
    const int acg  = (tid & 3) * 4;      // k sub-offset 0,4,8,12
    const int brow = tid >> 4;           // 0..15
    const int bcg  = (tid & 15) * 4;     // col sub-offset

    const float* Aptr = A + (size_t)(bm + arow) * K + acg;
    const float* Bptr = Bm + (size_t)brow * N + bn + bcg;

    float acc[4][4] = {};
    for (int kk = 0; kk < K; kk += 16) {
        float4 a4 = *(const float4*)(Aptr + kk);
        float4 b4 = *(const float4*)(Bptr + (size_t)kk * N);
        As[acg + 0][arow] = a4.x;
        As[acg + 1][arow] = a4.y;
        As[acg + 2][arow] = a4.z;
        As[acg + 3][arow] = a4.w;
        *(float4*)&Bs[brow][bcg] = b4;
        __syncthreads();
        #pragma unroll
        for (int k = 0; k < 16; k++) {
            float af[4], bf[4];
            #pragma unroll
            for (int i = 0; i < 4; i++) af[i] = As[k][ty * 4 + i];
            #pragma unroll
            for (int j = 0; j < 4; j++) bf[j] = Bs[k][tx * 4 + j];
            #pragma unroll
            for (int i = 0; i < 4; i++)
                #pragma unroll
                for (int j = 0; j < 4; j++)
                    acc[i][j] += af[i] * bf[j];
        }
        __syncthreads();
    }
    #pragma unroll
    for (int i = 0; i < 4; i++) {
        int row = bm + ty * 4 + i;
        #pragma unroll
        for (int j = 0; j < 4; j++) {
            int col = bn + tx * 4 + j;
            float c = acc[i][j];
            if (bias) c += bias[col];
            if (RELU) c = fmaxf(c, 0.f);
            if (res)  c += res[(size_t)row * N + col];
            C[(size_t)row * N + col] = c;
        }
    }
}

// ---------------- fused causal attention: one block per (b,h,t) ----------
__global__ __launch_bounds__(128)
void attn_kernel(const float* __restrict__ q, const float* __restrict__ k,
                 const float* __restrict__ v, float* __restrict__ y) {
    const int t = blockIdx.x, h = blockIdx.y, b = blockIdx.z;
    const int tid = threadIdx.x;
    __shared__ float qv[HDn];
    __shared__ float sc[Tn];
    __shared__ float red[128];

    const size_t base = (size_t)b * Tn * Cn + (size_t)h * HDn;
    if (tid < HDn) qv[tid] = q[base + (size_t)t * Cn + tid];
    __syncthreads();

    // scores (causal: s <= t)
    for (int s = tid; s <= t; s += 128) {
        const float* kp = k + base + (size_t)s * Cn;
        float d = 0.f;
        #pragma unroll
        for (int j = 0; j < HDn; j++) d += qv[j] * kp[j];
        sc[s] = d * 0.125f;   // 1/sqrt(64)
    }
    __syncthreads();

    // max
    float m = -1e30f;
    for (int s = tid; s <= t; s += 128) m = fmaxf(m, sc[s]);
    red[tid] = m; __syncthreads();
    for (int o = 64; o > 0; o >>= 1) {
        if (tid < o) red[tid] = fmaxf(red[tid], red[tid + o]);
        __syncthreads();
    }
    m = red[0];
    __syncthreads();

    // exp + sum
    float sum = 0.f;
    for (int s = tid; s <= t; s += 128) {
        float e = __expf(sc[s] - m);
        sc[s] = e;
        sum += e;
    }
    red[tid] = sum; __syncthreads();
    for (int o = 64; o > 0; o >>= 1) {
        if (tid < o) red[tid] += red[tid + o];
        __syncthreads();
    }
    const float inv = 1.f / red[0];
    __syncthreads();

    // y = (p @ v) / sum  — one thread per head dim
    if (tid < HDn) {
        float acc = 0.f;
        for (int s = 0; s <= t; s++)
            acc += sc[s] * v[base + (size_t)s * Cn + tid];
        y[base + (size_t)t * Cn + tid] = acc * inv;
    }
}

// ---------------- launch ----------------
extern "C" void kernel_launch(void* const* d_in, const int* in_sizes, int n_in,
                              void* d_out, int out_size) {
    const int*   idx   = (const int*)  d_in[0];
    const float* tok   = (const float*)d_in[1];
    const float* pos   = (const float*)d_in[2];
    const float* wq    = (const float*)d_in[3];
    const float* wk    = (const float*)d_in[4];
    const float* wv    = (const float*)d_in[5];
    const float* wo    = (const float*)d_in[6];
    const float* bo    = (const float*)d_in[7];
    const float* ln1g  = (const float*)d_in[8];
    const float* ln1b  = (const float*)d_in[9];
    const float* ln2g  = (const float*)d_in[10];
    const float* ln2b  = (const float*)d_in[11];
    const float* w1    = (const float*)d_in[12];
    const float* b1    = (const float*)d_in[13];
    const float* w2    = (const float*)d_in[14];
    const float* b2    = (const float*)d_in[15];
    const float* lnfg  = (const float*)d_in[16];
    const float* lnfb  = (const float*)d_in[17];
    const float* wlm   = (const float*)d_in[18];
    float* out = (float*)d_out;

    float *x, *xn, *q, *k, *v, *y, *h;
    cudaGetSymbolAddress((void**)&x,  g_x);
    cudaGetSymbolAddress((void**)&xn, g_xn);
    cudaGetSymbolAddress((void**)&q,  g_q);
    cudaGetSymbolAddress((void**)&k,  g_k);
    cudaGetSymbolAddress((void**)&v,  g_v);
    cudaGetSymbolAddress((void**)&y,  g_y);
    cudaGetSymbolAddress((void**)&h,  g_h);

    embed_kernel<<<BT, 256>>>(idx, tok, pos, x);

    const dim3 gridCC(Cn / 64, BT / 64);   // N=1024
    const dim3 gridCF(Fn / 64, BT / 64);   // N=4096
    const dim3 gridCV(Vn / 64, BT / 64);   // N=32000
    const dim3 gridAttn(Tn, Hn, Bn);

    for (int l = 0; l < Ln; l++) {
        const float* wql = wq + (size_t)l * Cn * Cn;
        const float* wkl = wk + (size_t)l * Cn * Cn;
        const float* wvl = wv + (size_t)l * Cn * Cn;
        const float* wol = wo + (size_t)l * Cn * Cn;
        const float* bol = bo + (size_t)l * Cn;
        const float* w1l = w1 + (size_t)l * Cn * Fn;
        const float* b1l = b1 + (size_t)l * Fn;
        const float* w2l = w2 + (size_t)l * Fn * Cn;
        const float* b2l = b2 + (size_t)l * Cn;

        ln_kernel<<<BT, 256>>>(x, ln1g + l * Cn, ln1b + l * Cn, xn);
        gemm64<false><<<gridCC, 256>>>(xn, wql, nullptr, nullptr, q, BT, Cn, Cn);
        gemm64<false><<<gridCC, 256>>>(xn, wkl, nullptr, nullptr, k, BT, Cn, Cn);
        gemm64<false><<<gridCC, 256>>>(xn, wvl, nullptr, nullptr, v, BT, Cn, Cn);
        attn_kernel<<<gridAttn, 128>>>(q, k, v, y);
        gemm64<false><<<gridCC, 256>>>(y, wol, bol, x, x, BT, Cn, Cn);

        ln_kernel<<<BT, 256>>>(x, ln2g + l * Cn, ln2b + l * Cn, xn);
        gemm64<true ><<<gridCF, 256>>>(xn, w1l, b1l, nullptr, h, BT, Fn, Cn);
        gemm64<false><<<gridCC, 256>>>(h,  w2l, b2l, x, x, BT, Cn, Fn);
    }

    ln_kernel<<<BT, 256>>>(x, lnfg, lnfb, xn);
    gemm64<false><<<gridCV, 256>>>(xn, wlm, nullptr, nullptr, out, BT, Vn, Cn);
}

// round 3
// speedup vs baseline: 1.5080x; 1.5080x over previous
#include <cuda_runtime.h>
#include <cuda_bf16.h>
#include <cstdint>
#include <math.h>

// GPT forward: B=4, T=512, L=12, C=1024, H=16, HD=64, F=4096, V=32000
#define Bn   4
#define Tn   512
#define Ln   12
#define Cn   1024
#define Hn   16
#define HDn  64
#define Fn   4096
#define Vn   32000
#define BT   (Bn * Tn)          // 2048

// ---------------- static scratch (no allocations allowed) ----------------
__device__ float g_x [BT * Cn];
__device__ float g_xn[BT * Cn];
__device__ float g_q [BT * Cn];
__device__ float g_k [BT * Cn];
__device__ float g_v [BT * Cn];
__device__ float g_y [BT * Cn];
__device__ float g_h [BT * Fn];
// transposed weights ([N,K] K-major, i.e. B col-major for mma .row.col)
__device__ float g_wqT[Ln * Cn * Cn];
__device__ float g_wkT[Ln * Cn * Cn];
__device__ float g_wvT[Ln * Cn * Cn];
__device__ float g_woT[Ln * Cn * Cn];
__device__ float g_w1T[Ln * Cn * Fn];
__device__ float g_w2T[Ln * Fn * Cn];
__device__ float g_wlmT[(size_t)Vn * Cn];

__device__ __forceinline__ uint32_t f2tf32(float f) {
    uint32_t u;
    asm("cvt.rna.tf32.f32 %0, %1;" : "=r"(u) : "f"(f));
    return u;
}

// ---------------- embedding ----------------
__global__ void embed_kernel(const int* __restrict__ idx,
                             const float* __restrict__ tok,
                             const float* __restrict__ pos,
                             float* __restrict__ x) {
    int row = blockIdx.x;
    int t = row & (Tn - 1);
    int token = idx[row];
    const float* tp = tok + (size_t)token * Cn;
    const float* pp = pos + (size_t)t * Cn;
    float* xp = x + (size_t)row * Cn;
    for (int c = threadIdx.x; c < Cn; c += 256)
        xp[c] = tp[c] + pp[c];
}

// ---------------- layernorm ----------------
__global__ void ln_kernel(const float* __restrict__ in,
                          const float* __restrict__ g,
                          const float* __restrict__ b,
                          float* __restrict__ out) {
    int row = blockIdx.x;
    int tid = threadIdx.x;
    const float* p = in + (size_t)row * Cn;
    float s = 0.f, sq = 0.f;
    for (int c = tid; c < Cn; c += 256) { float v = p[c]; s += v; sq += v * v; }
    __shared__ float rs[256], rq[256];
    rs[tid] = s; rq[tid] = sq; __syncthreads();
    for (int o = 128; o > 0; o >>= 1) {
        if (tid < o) { rs[tid] += rs[tid + o]; rq[tid] += rq[tid + o]; }
        __syncthreads();
    }
    float mean = rs[0] * (1.f / Cn);
    float var  = rq[0] * (1.f / Cn) - mean * mean;
    float inv  = rsqrtf(var + 1e-5f);
    float* op = out + (size_t)row * Cn;
    for (int c = tid; c < Cn; c += 256)
        op[c] = (p[c] - mean) * inv * g[c] + b[c];
}

// ---------------- transpose [R,Ccol] -> [Ccol,R] per z-slab ----------------
__global__ void transpose_k(const float* __restrict__ in, float* __restrict__ out,
                            int R, int Ccol) {
    __shared__ float t[32][33];
    const float* ip = in + (size_t)blockIdx.z * R * Ccol;
    float* op = out + (size_t)blockIdx.z * R * Ccol;
    int c0 = blockIdx.x * 32, r0 = blockIdx.y * 32;
    for (int i = threadIdx.y; i < 32; i += 8)
        t[i][threadIdx.x] = ip[(size_t)(r0 + i) * Ccol + c0 + threadIdx.x];
    __syncthreads();
    for (int i = threadIdx.y; i < 32; i += 8)
        op[(size_t)(c0 + i) * R + r0 + threadIdx.x] = t[threadIdx.x][i];
}

// ---------------- tf32 mma.sync GEMM: C[M,N] = A[M,K] @ Bt[N,K]^T ----------
// CTA 128x128, BK=32, 8 warps, warp tile 64x32 (4x4 of m16n8k8).
// SMEM rows padded to 36 floats -> conflict-free fragment LDS.
#define SMPAD 36
#define ATILE (128 * SMPAD)
#define BUFSZ (2 * ATILE)                      // A + B per buffer (floats)
#define GEMM_SMEM_DYN (2 * BUFSZ * 4)          // 73728 bytes

template<bool RELU>
__global__ __launch_bounds__(256, 1)
void gemm_mma(const float* __restrict__ A, const float* __restrict__ Bt,
              const float* __restrict__ bias, const float* __restrict__ res,
              float* __restrict__ C, int N, int K) {
    extern __shared__ float sm[];
    const int tid = threadIdx.x;
    const int lane = tid & 31, wid = tid >> 5;
    const int warp_m = (wid & 1) << 6;         // 0 or 64
    const int warp_n = (wid >> 1) << 5;        // 0,32,64,96
    const int m0 = blockIdx.y * 128;
    const int n0 = blockIdx.x * 128;

    const float* Ag = A  + (size_t)m0 * K;
    const float* Bg = Bt + (size_t)n0 * K;

    // per-thread load slots: 4 float4 each from A and B tile (128x32)
    int ldr[4], ldc[4];
    #pragma unroll
    for (int j = 0; j < 4; j++) {
        int slot = j * 256 + tid;
        ldr[j] = slot >> 3;                    // row 0..127
        ldc[j] = (slot & 7) << 2;              // k col 0,4,..,28
    }

    // ---- load chunk 0 directly to smem ----
    #pragma unroll
    for (int j = 0; j < 4; j++) {
        float4 a4 = *(const float4*)(Ag + (size_t)ldr[j] * K + ldc[j]);
        float4 b4 = *(const float4*)(Bg + (size_t)ldr[j] * K + ldc[j]);
        uint32_t* pA = (uint32_t*)(sm + ldr[j] * SMPAD + ldc[j]);
        uint32_t* pB = (uint32_t*)(sm + ATILE + ldr[j] * SMPAD + ldc[j]);
        pA[0] = f2tf32(a4.x); pA[1] = f2tf32(a4.y);
        pA[2] = f2tf32(a4.z); pA[3] = f2tf32(a4.w);
        pB[0] = f2tf32(b4.x); pB[1] = f2tf32(b4.y);
        pB[2] = f2tf32(b4.z); pB[3] = f2tf32(b4.w);
    }
    __syncthreads();

    float acc[4][4][4];
    #pragma unroll
    for (int mi = 0; mi < 4; mi++)
        #pragma unroll
        for (int ni = 0; ni < 4; ni++)
            #pragma unroll
            for (int r = 0; r < 4; r++) acc[mi][ni][r] = 0.f;

    const int nk = K >> 5;
    for (int it = 0; it < nk; ++it) {
        const int cur = it & 1;
        const float* Ac = sm + cur * BUFSZ;
        const float* Bc = Ac + ATILE;

        // prefetch next chunk into registers
        float4 pa[4], pb[4];
        if (it + 1 < nk) {
            const int kk = (it + 1) << 5;
            #pragma unroll
            for (int j = 0; j < 4; j++) {
                pa[j] = *(const float4*)(Ag + (size_t)ldr[j] * K + kk + ldc[j]);
                pb[j] = *(const float4*)(Bg + (size_t)ldr[j] * K + kk + ldc[j]);
            }
        }

        // compute on current buffer: 4 k-steps of 8
        #pragma unroll
        for (int ks = 0; ks < 4; ks++) {
            const int kb = ks * 8;
            uint32_t af[4][4], bf[4][2];
            #pragma unroll
            for (int mi = 0; mi < 4; mi++) {
                int rl = warp_m + mi * 16 + (lane >> 2);
                int kc = kb + (lane & 3);
                af[mi][0] = __float_as_uint(Ac[rl * SMPAD + kc]);
                af[mi][1] = __float_as_uint(Ac[(rl + 8) * SMPAD + kc]);
                af[mi][2] = __float_as_uint(Ac[rl * SMPAD + kc + 4]);
                af[mi][3] = __float_as_uint(Ac[(rl + 8) * SMPAD + kc + 4]);
            }
            #pragma unroll
            for (int ni = 0; ni < 4; ni++) {
                int nn = warp_n + ni * 8 + (lane >> 2);
                int kc = kb + (lane & 3);
                bf[ni][0] = __float_as_uint(Bc[nn * SMPAD + kc]);
                bf[ni][1] = __float_as_uint(Bc[nn * SMPAD + kc + 4]);
            }
            #pragma unroll
            for (int mi = 0; mi < 4; mi++)
                #pragma unroll
                for (int ni = 0; ni < 4; ni++) {
                    asm volatile(
                        "mma.sync.aligned.m16n8k8.row.col.f32.tf32.tf32.f32 "
                        "{%0,%1,%2,%3}, {%4,%5,%6,%7}, {%8,%9}, {%0,%1,%2,%3};"
                        : "+f"(acc[mi][ni][0]), "+f"(acc[mi][ni][1]),
                          "+f"(acc[mi][ni][2]), "+f"(acc[mi][ni][3])
                        : "r"(af[mi][0]), "r"(af[mi][1]), "r"(af[mi][2]), "r"(af[mi][3]),
                          "r"(bf[ni][0]), "r"(bf[ni][1]));
                }
        }

        // store prefetched chunk into the other buffer
        if (it + 1 < nk) {
            float* An = sm + ((it + 1) & 1) * BUFSZ;
            float* Bnx = An + ATILE;
            #pragma unroll
            for (int j = 0; j < 4; j++) {
                uint32_t* pA = (uint32_t*)(An + ldr[j] * SMPAD + ldc[j]);
                uint32_t* pB = (uint32_t*)(Bnx + ldr[j] * SMPAD + ldc[j]);
                pA[0] = f2tf32(pa[j].x); pA[1] = f2tf32(pa[j].y);
                pA[2] = f2tf32(pa[j].z); pA[3] = f2tf32(pa[j].w);
                pB[0] = f2tf32(pb[j].x); pB[1] = f2tf32(pb[j].y);
                pB[2] = f2tf32(pb[j].z); pB[3] = f2tf32(pb[j].w);
            }
        }
        __syncthreads();
    }

    // ---- epilogue: c0,c1 at (row, col..col+1), c2,c3 at (row+8, ..) ----
    #pragma unroll
    for (int mi = 0; mi < 4; mi++) {
        int row = m0 + warp_m + mi * 16 + (lane >> 2);
        #pragma unroll
        for (int ni = 0; ni < 4; ni++) {
            int col = n0 + warp_n + ni * 8 + ((lane & 3) << 1);
            float v0 = acc[mi][ni][0], v1 = acc[mi][ni][1];
            float v2 = acc[mi][ni][2], v3 = acc[mi][ni][3];
            if (bias) {
                float b0 = bias[col], b1 = bias[col + 1];
                v0 += b0; v1 += b1; v2 += b0; v3 += b1;
            }
            if (RELU) {
                v0 = fmaxf(v0, 0.f); v1 = fmaxf(v1, 0.f);
                v2 = fmaxf(v2, 0.f); v3 = fmaxf(v3, 0.f);
            }
            if (res) {
                const float2 r0 = *(const float2*)(res + (size_t)row * N + col);
                const float2 r1 = *(const float2*)(res + (size_t)(row + 8) * N + col);
                v0 += r0.x; v1 += r0.y; v2 += r1.x; v3 += r1.y;
            }
            *(float2*)(C + (size_t)row * N + col) = make_float2(v0, v1);
            *(float2*)(C + (size_t)(row + 8) * N + col) = make_float2(v2, v3);
        }
    }
}

// ---------------- fused causal attention: one block per (b,h,t) ----------
__global__ __launch_bounds__(128)
void attn_kernel(const float* __restrict__ q, const float* __restrict__ k,
                 const float* __restrict__ v, float* __restrict__ y) {
    const int t = blockIdx.x, h = blockIdx.y, b = blockIdx.z;
    const int tid = threadIdx.x;
    __shared__ float qv[HDn];
    __shared__ float sc[Tn];
    __shared__ float red[128];

    const size_t base = (size_t)b * Tn * Cn + (size_t)h * HDn;
    if (tid < HDn) qv[tid] = q[base + (size_t)t * Cn + tid];
    __syncthreads();

    for (int s = tid; s <= t; s += 128) {
        const float* kp = k + base + (size_t)s * Cn;
        float d = 0.f;
        #pragma unroll
        for (int j = 0; j < HDn; j++) d += qv[j] * kp[j];
        sc[s] = d * 0.125f;
    }
    __syncthreads();

    float m = -1e30f;
    for (int s = tid; s <= t; s += 128) m = fmaxf(m, sc[s]);
    red[tid] = m; __syncthreads();
    for (int o = 64; o > 0; o >>= 1) {
        if (tid < o) red[tid] = fmaxf(red[tid], red[tid + o]);
        __syncthreads();
    }
    m = red[0];
    __syncthreads();

    float sum = 0.f;
    for (int s = tid; s <= t; s += 128) {
        float e = __expf(sc[s] - m);
        sc[s] = e;
        sum += e;
    }
    red[tid] = sum; __syncthreads();
    for (int o = 64; o > 0; o >>= 1) {
        if (tid < o) red[tid] += red[tid + o];
        __syncthreads();
    }
    const float inv = 1.f / red[0];
    __syncthreads();

    if (tid < HDn) {
        float acc = 0.f;
        for (int s = 0; s <= t; s++)
            acc += sc[s] * v[base + (size_t)s * Cn + tid];
        y[base + (size_t)t * Cn + tid] = acc * inv;
    }
}

// ---------------- launch ----------------
extern "C" void kernel_launch(void* const* d_in, const int* in_sizes, int n_in,
                              void* d_out, int out_size) {
    const int*   idx   = (const int*)  d_in[0];
    const float* tok   = (const float*)d_in[1];
    const float* pos   = (const float*)d_in[2];
    const float* wq    = (const float*)d_in[3];
    const float* wk    = (const float*)d_in[4];
    const float* wv    = (const float*)d_in[5];
    const float* wo    = (const float*)d_in[6];
    const float* bo    = (const float*)d_in[7];
    const float* ln1g  = (const float*)d_in[8];
    const float* ln1b  = (const float*)d_in[9];
    const float* ln2g  = (const float*)d_in[10];
    const float* ln2b  = (const float*)d_in[11];
    const float* w1    = (const float*)d_in[12];
    const float* b1    = (const float*)d_in[13];
    const float* w2    = (const float*)d_in[14];
    const float* b2    = (const float*)d_in[15];
    const float* lnfg  = (const float*)d_in[16];
    const float* lnfb  = (const float*)d_in[17];
    const float* wlm   = (const float*)d_in[18];
    float* out = (float*)d_out;

    float *x, *xn, *q, *k, *v, *y, *h;
    float *wqT, *wkT, *wvT, *woT, *w1T, *w2T, *wlmT;
    cudaGetSymbolAddress((void**)&x,  g_x);
    cudaGetSymbolAddress((void**)&xn, g_xn);
    cudaGetSymbolAddress((void**)&q,  g_q);
    cudaGetSymbolAddress((void**)&k,  g_k);
    cudaGetSymbolAddress((void**)&v,  g_v);
    cudaGetSymbolAddress((void**)&y,  g_y);
    cudaGetSymbolAddress((void**)&h,  g_h);
    cudaGetSymbolAddress((void**)&wqT, g_wqT);
    cudaGetSymbolAddress((void**)&wkT, g_wkT);
    cudaGetSymbolAddress((void**)&wvT, g_wvT);
    cudaGetSymbolAddress((void**)&woT, g_woT);
    cudaGetSymbolAddress((void**)&w1T, g_w1T);
    cudaGetSymbolAddress((void**)&w2T, g_w2T);
    cudaGetSymbolAddress((void**)&wlmT, g_wlmT);

    cudaFuncSetAttribute(gemm_mma<false>, cudaFuncAttributeMaxDynamicSharedMemorySize, GEMM_SMEM_DYN);
    cudaFuncSetAttribute(gemm_mma<true>,  cudaFuncAttributeMaxDynamicSharedMemorySize, GEMM_SMEM_DYN);

    // transpose all weights to [N,K]
    dim3 tb(32, 8);
    transpose_k<<<dim3(Cn / 32, Cn / 32, Ln), tb>>>(wq, wqT, Cn, Cn);
    transpose_k<<<dim3(Cn / 32, Cn / 32, Ln), tb>>>(wk, wkT, Cn, Cn);
    transpose_k<<<dim3(Cn / 32, Cn / 32, Ln), tb>>>(wv, wvT, Cn, Cn);
    transpose_k<<<dim3(Cn / 32, Cn / 32, Ln), tb>>>(wo, woT, Cn, Cn);
    transpose_k<<<dim3(Fn / 32, Cn / 32, Ln), tb>>>(w1, w1T, Cn, Fn);
    transpose_k<<<dim3(Cn / 32, Fn / 32, Ln), tb>>>(w2, w2T, Fn, Cn);
    transpose_k<<<dim3(Vn / 32, Cn / 32, 1),  tb>>>(wlm, wlmT, Cn, Vn);

    embed_kernel<<<BT, 256>>>(idx, tok, pos, x);

    const dim3 gCC(Cn / 128, BT / 128);    // 8 x 16
    const dim3 gCF(Fn / 128, BT / 128);    // 32 x 16
    const dim3 gCV(Vn / 128, BT / 128);    // 250 x 16
    const dim3 gAttn(Tn, Hn, Bn);

    for (int l = 0; l < Ln; l++) {
        const float* wqTl = wqT + (size_t)l * Cn * Cn;
        const float* wkTl = wkT + (size_t)l * Cn * Cn;
        const float* wvTl = wvT + (size_t)l * Cn * Cn;
        const float* woTl = woT + (size_t)l * Cn * Cn;
        const float* bol  = bo + (size_t)l * Cn;
        const float* w1Tl = w1T + (size_t)l * Cn * Fn;
        const float* b1l  = b1 + (size_t)l * Fn;
        const float* w2Tl = w2T + (size_t)l * Fn * Cn;
        const float* b2l  = b2 + (size_t)l * Cn;

        ln_kernel<<<BT, 256>>>(x, ln1g + l * Cn, ln1b + l * Cn, xn);
        gemm_mma<false><<<gCC, 256, GEMM_SMEM_DYN>>>(xn, wqTl, nullptr, nullptr, q, Cn, Cn);
        gemm_mma<false><<<gCC, 256, GEMM_SMEM_DYN>>>(xn, wkTl, nullptr, nullptr, k, Cn, Cn);
        gemm_mma<false><<<gCC, 256, GEMM_SMEM_DYN>>>(xn, wvTl, nullptr, nullptr, v, Cn, Cn);
        attn_kernel<<<gAttn, 128>>>(q, k, v, y);
        gemm_mma<false><<<gCC, 256, GEMM_SMEM_DYN>>>(y, woTl, bol, x, x, Cn, Cn);

        ln_kernel<<<BT, 256>>>(x, ln2g + l * Cn, ln2b + l * Cn, xn);
        gemm_mma<true ><<<gCF, 256, GEMM_SMEM_DYN>>>(xn, w1Tl, b1l, nullptr, h, Fn, Cn);
        gemm_mma<false><<<gCC, 256, GEMM_SMEM_DYN>>>(h,  w2Tl, b2l, x, x, Cn, Fn);
    }

    ln_kernel<<<BT, 256>>>(x, lnfg, lnfb, xn);
    gemm_mma<false><<<gCV, 256, GEMM_SMEM_DYN>>>(xn, wlmT, nullptr, nullptr, out, Vn, Cn);
}

// round 4
// speedup vs baseline: 5.2747x; 3.4978x over previous
#include <cuda_runtime.h>
#include <cstdint>
#include <math.h>

// GPT forward: B=4, T=512, L=12, C=1024, H=16, HD=64, F=4096, V=32000
#define Bn   4
#define Tn   512
#define Ln   12
#define Cn   1024
#define Hn   16
#define HDn  64
#define Fn   4096
#define Vn   32000
#define BT   (Bn * Tn)          // 2048

// ---------------- static scratch (no allocations allowed) ----------------
__device__ float g_x [BT * Cn];
__device__ float g_xn[BT * Cn];
__device__ float g_q [BT * Cn];
__device__ float g_k [BT * Cn];
__device__ float g_v [BT * Cn];
__device__ float g_y [BT * Cn];
__device__ float g_h [BT * Fn];
// tf32-rounded weights (same [K,N] layout as inputs)
__device__ float g_wqR[Ln * Cn * Cn];
__device__ float g_wkR[Ln * Cn * Cn];
__device__ float g_wvR[Ln * Cn * Cn];
__device__ float g_woR[Ln * Cn * Cn];
__device__ float g_w1R[Ln * Cn * Fn];
__device__ float g_w2R[Ln * Fn * Cn];
__device__ float g_wlmR[(size_t)Vn * Cn];

__device__ __forceinline__ uint32_t f2tf32(float f) {
    uint32_t u;
    asm("cvt.rna.tf32.f32 %0, %1;" : "=r"(u) : "f"(f));
    return u;
}
__device__ __forceinline__ float roundtf(float f) {
    return __uint_as_float(f2tf32(f));
}
__device__ __forceinline__ uint32_t smem_u32(const void* p) {
    uint32_t a;
    asm("{ .reg .u64 t; cvta.to.shared.u64 t, %1; cvt.u32.u64 %0, t; }"
        : "=r"(a) : "l"(p));
    return a;
}
__device__ __forceinline__ void cp16(void* s, const void* g) {
    asm volatile("cp.async.cg.shared.global [%0], [%1], 16;"
                 :: "r"(smem_u32(s)), "l"(g) : "memory");
}
#define CP_COMMIT() asm volatile("cp.async.commit_group;" ::: "memory")
#define CP_WAIT1()  asm volatile("cp.async.wait_group 1;" ::: "memory")
#define CP_WAIT0()  asm volatile("cp.async.wait_group 0;" ::: "memory")

// ---------------- one-shot weight rounding (elementwise, coalesced) ------
#define N_QKVO (Ln * Cn * Cn)          // 12,582,912
#define N_FF   (Ln * Cn * Fn)          // 50,331,648
#define N_LM   ((size_t)Vn * Cn)       // 32,768,000

__global__ void round_weights(const float* wq, const float* wk, const float* wv,
                              const float* wo, const float* w1, const float* w2,
                              const float* wlm,
                              float* wqR, float* wkR, float* wvR, float* woR,
                              float* w1R, float* w2R, float* wlmR) {
    const float* in; float* out; size_t n;
    switch (blockIdx.y) {
        case 0: in = wq;  out = wqR;  n = N_QKVO; break;
        case 1: in = wk;  out = wkR;  n = N_QKVO; break;
        case 2: in = wv;  out = wvR;  n = N_QKVO; break;
        case 3: in = wo;  out = woR;  n = N_QKVO; break;
        case 4: in = w1;  out = w1R;  n = N_FF;   break;
        case 5: in = w2;  out = w2R;  n = N_FF;   break;
        default: in = wlm; out = wlmR; n = N_LM;  break;
    }
    size_t i = ((size_t)blockIdx.x * 256 + threadIdx.x) * 4;
    if (i >= n) return;
    float4 v = *(const float4*)(in + i);
    v.x = roundtf(v.x); v.y = roundtf(v.y);
    v.z = roundtf(v.z); v.w = roundtf(v.w);
    *(float4*)(out + i) = v;
}

// ---------------- embedding (x stays fp32: residual stream) --------------
__global__ void embed_kernel(const int* __restrict__ idx,
                             const float* __restrict__ tok,
                             const float* __restrict__ pos,
                             float* __restrict__ x) {
    int row = blockIdx.x;
    int t = row & (Tn - 1);
    int token = idx[row];
    const float* tp = tok + (size_t)token * Cn;
    const float* pp = pos + (size_t)t * Cn;
    float* xp = x + (size_t)row * Cn;
    for (int c = threadIdx.x; c < Cn; c += 256)
        xp[c] = tp[c] + pp[c];
}

// ---------------- layernorm (output tf32-rounded: feeds GEMM A) ----------
__global__ void ln_kernel(const float* __restrict__ in,
                          const float* __restrict__ g,
                          const float* __restrict__ b,
                          float* __restrict__ out) {
    int row = blockIdx.x;
    int tid = threadIdx.x;
    const float* p = in + (size_t)row * Cn;
    float s = 0.f, sq = 0.f;
    for (int c = tid; c < Cn; c += 256) { float v = p[c]; s += v; sq += v * v; }
    __shared__ float rs[256], rq[256];
    rs[tid] = s; rq[tid] = sq; __syncthreads();
    for (int o = 128; o > 0; o >>= 1) {
        if (tid < o) { rs[tid] += rs[tid + o]; rq[tid] += rq[tid + o]; }
        __syncthreads();
    }
    float mean = rs[0] * (1.f / Cn);
    float var  = rq[0] * (1.f / Cn) - mean * mean;
    float inv  = rsqrtf(var + 1e-5f);
    float* op = out + (size_t)row * Cn;
    for (int c = tid; c < Cn; c += 256)
        op[c] = roundtf((p[c] - mean) * inv * g[c] + b[c]);
}

// ---------------- tf32 mma GEMM: C[M,N] = A[M,K] @ B[K,N] ----------------
// CTA 128x128, BK=32, 8 warps (warp tile 64x32), cp.async double buffer,
// 2 CTAs/SM. A smem [128][36]; B smem [32][136] (both conflict-free).
#define APAD 36
#define BPAD 136
#define ASZ (128 * APAD)               // floats
#define BSZ (32 * BPAD)
#define STAGEF (ASZ + BSZ)             // 8960 floats
#define GEMM_SMEM_DYN (2 * STAGEF * 4) // 71680 bytes

template<bool RELU, bool ROUND>
__global__ __launch_bounds__(256, 2)
void gemm_mma(const float* __restrict__ A, const float* __restrict__ B,
              const float* __restrict__ bias, const float* __restrict__ res,
              float* __restrict__ C, int N, int K) {
    extern __shared__ float sm[];
    const int tid = threadIdx.x;
    const int lane = tid & 31, wid = tid >> 5;
    const int warp_m = (wid & 1) << 6;     // 0 or 64
    const int warp_n = (wid >> 1) << 5;    // 0,32,64,96
    const int m0 = blockIdx.y * 128;
    const int n0 = blockIdx.x * 128;

    // A slots: tile 128 x 32, 4 float4 per thread
    // B slots: tile 32 x 128, 4 float4 per thread
    const float* aptr[4]; const float* bptr[4];
    int saoff[4], sboff[4];
    #pragma unroll
    for (int j = 0; j < 4; j++) {
        int ia = j * 256 + tid;
        int ar = ia >> 3, ac = (ia & 7) << 2;       // row 0..127, k 0,4..28
        aptr[j] = A + (size_t)(m0 + ar) * K + ac;
        saoff[j] = ar * APAD + ac;
        int ib = j * 256 + tid;
        int bk = ib >> 5, bc = (ib & 31) << 2;      // k 0..31, n 0,4..124
        bptr[j] = B + (size_t)bk * N + n0 + bc;
        sboff[j] = bk * BPAD + bc;
    }

    const int nk = K >> 5;

    // prologue: stage 0
    {
        float* As = sm; float* Bs = sm + ASZ;
        #pragma unroll
        for (int j = 0; j < 4; j++) {
            cp16(As + saoff[j], aptr[j]);
            cp16(Bs + sboff[j], bptr[j]);
        }
        CP_COMMIT();
    }

    float acc[4][4][4];
    #pragma unroll
    for (int mi = 0; mi < 4; mi++)
        #pragma unroll
        for (int ni = 0; ni < 4; ni++)
            #pragma unroll
            for (int r = 0; r < 4; r++) acc[mi][ni][r] = 0.f;

    for (int it = 0; it < nk; ++it) {
        if (it + 1 < nk) {
            const int kk = (it + 1) << 5;
            float* As = sm + ((it + 1) & 1) * STAGEF;
            float* Bs = As + ASZ;
            #pragma unroll
            for (int j = 0; j < 4; j++) {
                cp16(As + saoff[j], aptr[j] + kk);
                cp16(Bs + sboff[j], bptr[j] + (size_t)kk * N);
            }
            CP_COMMIT();
            CP_WAIT1();
        } else {
            CP_WAIT0();
        }
        __syncthreads();

        const float* Ac = sm + (it & 1) * STAGEF;
        const float* Bc = Ac + ASZ;
        #pragma unroll
        for (int ks = 0; ks < 4; ks++) {
            const int kb = ks * 8;
            uint32_t af[4][4], bf[4][2];
            #pragma unroll
            for (int mi = 0; mi < 4; mi++) {
                int rl = warp_m + mi * 16 + (lane >> 2);
                int kc = kb + (lane & 3);
                af[mi][0] = __float_as_uint(Ac[rl * APAD + kc]);
                af[mi][1] = __float_as_uint(Ac[(rl + 8) * APAD + kc]);
                af[mi][2] = __float_as_uint(Ac[rl * APAD + kc + 4]);
                af[mi][3] = __float_as_uint(Ac[(rl + 8) * APAD + kc + 4]);
            }
            #pragma unroll
            for (int ni = 0; ni < 4; ni++) {
                int nn = warp_n + ni * 8 + (lane >> 2);
                int kc = kb + (lane & 3);
                bf[ni][0] = __float_as_uint(Bc[kc * BPAD + nn]);
                bf[ni][1] = __float_as_uint(Bc[(kc + 4) * BPAD + nn]);
            }
            #pragma unroll
            for (int mi = 0; mi < 4; mi++)
                #pragma unroll
                for (int ni = 0; ni < 4; ni++) {
                    asm volatile(
                        "mma.sync.aligned.m16n8k8.row.col.f32.tf32.tf32.f32 "
                        "{%0,%1,%2,%3}, {%4,%5,%6,%7}, {%8,%9}, {%0,%1,%2,%3};"
                        : "+f"(acc[mi][ni][0]), "+f"(acc[mi][ni][1]),
                          "+f"(acc[mi][ni][2]), "+f"(acc[mi][ni][3])
                        : "r"(af[mi][0]), "r"(af[mi][1]), "r"(af[mi][2]), "r"(af[mi][3]),
                          "r"(bf[ni][0]), "r"(bf[ni][1]));
                }
        }
        __syncthreads();
    }

    // epilogue
    #pragma unroll
    for (int mi = 0; mi < 4; mi++) {
        int row = m0 + warp_m + mi * 16 + (lane >> 2);
        #pragma unroll
        for (int ni = 0; ni < 4; ni++) {
            int col = n0 + warp_n + ni * 8 + ((lane & 3) << 1);
            float v0 = acc[mi][ni][0], v1 = acc[mi][ni][1];
            float v2 = acc[mi][ni][2], v3 = acc[mi][ni][3];
            if (bias) {
                float b0 = bias[col], b1 = bias[col + 1];
                v0 += b0; v1 += b1; v2 += b0; v3 += b1;
            }
            if (RELU) {
                v0 = fmaxf(v0, 0.f); v1 = fmaxf(v1, 0.f);
                v2 = fmaxf(v2, 0.f); v3 = fmaxf(v3, 0.f);
            }
            if (res) {
                const float2 r0 = *(const float2*)(res + (size_t)row * N + col);
                const float2 r1 = *(const float2*)(res + (size_t)(row + 8) * N + col);
                v0 += r0.x; v1 += r0.y; v2 += r1.x; v3 += r1.y;
            }
            if (ROUND) {
                v0 = roundtf(v0); v1 = roundtf(v1);
                v2 = roundtf(v2); v3 = roundtf(v3);
            }
            *(float2*)(C + (size_t)row * N + col) = make_float2(v0, v1);
            *(float2*)(C + (size_t)(row + 8) * N + col) = make_float2(v2, v3);
        }
    }
}

// ---------------- flash attention: one block = 64 t-rows of one (b,h) ----
__global__ __launch_bounds__(64)
void attn_flash(const float* __restrict__ q, const float* __restrict__ k,
                const float* __restrict__ v, float* __restrict__ y) {
    const int tt = blockIdx.x, h = blockIdx.y, b = blockIdx.z;
    const int tid = threadIdx.x;                 // 0..63
    __shared__ float ks[64 * 64];
    __shared__ float vs[64 * 64];
    const size_t base = (size_t)b * Tn * Cn + (size_t)h * HDn;
    const int t0 = tt * 64;

    // stage q tile, copy own row into registers (pre-scaled)
    for (int i = tid; i < 4096; i += 64)
        ks[i] = q[base + (size_t)(t0 + (i >> 6)) * Cn + (i & 63)];
    __syncthreads();
    float qr[64];
    #pragma unroll
    for (int d = 0; d < 64; d++) qr[d] = ks[tid * 64 + d] * 0.125f;
    __syncthreads();

    float m = -1e30f, l = 0.f;
    float acc[64];
    #pragma unroll
    for (int d = 0; d < 64; d++) acc[d] = 0.f;

    for (int st = 0; st <= tt; ++st) {
        const int s0 = st * 64;
        for (int i = tid; i < 4096; i += 64) {
            size_t gi = base + (size_t)(s0 + (i >> 6)) * Cn + (i & 63);
            ks[i] = k[gi];
            vs[i] = v[gi];
        }
        __syncthreads();
        const int smax = (st == tt) ? tid : 63;

        // pass 1: tile max
        float tm = m;
        for (int s = 0; s <= smax; ++s) {
            const float4* kp = (const float4*)(ks + s * 64);
            float d = 0.f;
            #pragma unroll
            for (int j = 0; j < 16; j++) {
                float4 kv = kp[j];
                d += qr[4*j] * kv.x + qr[4*j+1] * kv.y
                   + qr[4*j+2] * kv.z + qr[4*j+3] * kv.w;
            }
            tm = fmaxf(tm, d);
        }
        float scale = __expf(m - tm);
        l *= scale;
        #pragma unroll
        for (int d = 0; d < 64; d++) acc[d] *= scale;
        m = tm;

        // pass 2: exp + accumulate
        for (int s = 0; s <= smax; ++s) {
            const float4* kp = (const float4*)(ks + s * 64);
            float d = 0.f;
            #pragma unroll
            for (int j = 0; j < 16; j++) {
                float4 kv = kp[j];
                d += qr[4*j] * kv.x + qr[4*j+1] * kv.y
                   + qr[4*j+2] * kv.z + qr[4*j+3] * kv.w;
            }
            float p = __expf(d - m);
            l += p;
            const float4* vp = (const float4*)(vs + s * 64);
            #pragma unroll
            for (int j = 0; j < 16; j++) {
                float4 vv = vp[j];
                acc[4*j]   += p * vv.x; acc[4*j+1] += p * vv.y;
                acc[4*j+2] += p * vv.z; acc[4*j+3] += p * vv.w;
            }
        }
        __syncthreads();
    }

    // write out, tf32-rounded (y feeds the WO GEMM as A)
    const float inv = 1.f / l;
    #pragma unroll
    for (int d = 0; d < 64; d++) ks[tid * 64 + d] = acc[d] * inv;
    __syncthreads();
    for (int i = tid; i < 4096; i += 64)
        y[base + (size_t)(t0 + (i >> 6)) * Cn + (i & 63)] = roundtf(ks[i]);
}

// ---------------- launch ----------------
extern "C" void kernel_launch(void* const* d_in, const int* in_sizes, int n_in,
                              void* d_out, int out_size) {
    const int*   idx   = (const int*)  d_in[0];
    const float* tok   = (const float*)d_in[1];
    const float* pos   = (const float*)d_in[2];
    const float* wq    = (const float*)d_in[3];
    const float* wk    = (const float*)d_in[4];
    const float* wv    = (const float*)d_in[5];
    const float* wo    = (const float*)d_in[6];
    const float* bo    = (const float*)d_in[7];
    const float* ln1g  = (const float*)d_in[8];
    const float* ln1b  = (const float*)d_in[9];
    const float* ln2g  = (const float*)d_in[10];
    const float* ln2b  = (const float*)d_in[11];
    const float* w1    = (const float*)d_in[12];
    const float* b1    = (const float*)d_in[13];
    const float* w2    = (const float*)d_in[14];
    const float* b2    = (const float*)d_in[15];
    const float* lnfg  = (const float*)d_in[16];
    const float* lnfb  = (const float*)d_in[17];
    const float* wlm   = (const float*)d_in[18];
    float* out = (float*)d_out;

    float *x, *xn, *q, *k, *v, *y, *h;
    float *wqR, *wkR, *wvR, *woR, *w1R, *w2R, *wlmR;
    cudaGetSymbolAddress((void**)&x,  g_x);
    cudaGetSymbolAddress((void**)&xn, g_xn);
    cudaGetSymbolAddress((void**)&q,  g_q);
    cudaGetSymbolAddress((void**)&k,  g_k);
    cudaGetSymbolAddress((void**)&v,  g_v);
    cudaGetSymbolAddress((void**)&y,  g_y);
    cudaGetSymbolAddress((void**)&h,  g_h);
    cudaGetSymbolAddress((void**)&wqR, g_wqR);
    cudaGetSymbolAddress((void**)&wkR, g_wkR);
    cudaGetSymbolAddress((void**)&wvR, g_wvR);
    cudaGetSymbolAddress((void**)&woR, g_woR);
    cudaGetSymbolAddress((void**)&w1R, g_w1R);
    cudaGetSymbolAddress((void**)&w2R, g_w2R);
    cudaGetSymbolAddress((void**)&wlmR, g_wlmR);

    cudaFuncSetAttribute(gemm_mma<false, false>,
                         cudaFuncAttributeMaxDynamicSharedMemorySize, GEMM_SMEM_DYN);
    cudaFuncSetAttribute(gemm_mma<true, true>,
                         cudaFuncAttributeMaxDynamicSharedMemorySize, GEMM_SMEM_DYN);

    // launch 0: round all weights to tf32 (elementwise, one launch)
    round_weights<<<dim3(N_FF / 4 / 256, 7), 256>>>(
        wq, wk, wv, wo, w1, w2, wlm, wqR, wkR, wvR, woR, w1R, w2R, wlmR);
    // launch 1
    embed_kernel<<<BT, 256>>>(idx, tok, pos, x);

    const dim3 gCC(Cn / 128, BT / 128);    // 8 x 16
    const dim3 gCF(Fn / 128, BT / 128);    // 32 x 16
    const dim3 gCV(Vn / 128, BT / 128);    // 250 x 16
    const dim3 gAttn(Tn / 64, Hn, Bn);     // 8 x 16 x 4

    for (int l = 0; l < Ln; l++) {
        const float* wqRl = wqR + (size_t)l * Cn * Cn;
        const float* wkRl = wkR + (size_t)l * Cn * Cn;
        const float* wvRl = wvR + (size_t)l * Cn * Cn;
        const float* woRl = woR + (size_t)l * Cn * Cn;
        const float* bol  = bo + (size_t)l * Cn;
        const float* w1Rl = w1R + (size_t)l * Cn * Fn;
        const float* b1l  = b1 + (size_t)l * Fn;
        const float* w2Rl = w2R + (size_t)l * Fn * Cn;
        const float* b2l  = b2 + (size_t)l * Cn;

        ln_kernel<<<BT, 256>>>(x, ln1g + l * Cn, ln1b + l * Cn, xn);
        gemm_mma<false, false><<<gCC, 256, GEMM_SMEM_DYN>>>(xn, wqRl, nullptr, nullptr, q, Cn, Cn);
        gemm_mma<false, false><<<gCC, 256, GEMM_SMEM_DYN>>>(xn, wkRl, nullptr, nullptr, k, Cn, Cn);
        gemm_mma<false, false><<<gCC, 256, GEMM_SMEM_DYN>>>(xn, wvRl, nullptr, nullptr, v, Cn, Cn);
        attn_flash<<<gAttn, 64>>>(q, k, v, y);
        gemm_mma<false, false><<<gCC, 256, GEMM_SMEM_DYN>>>(y, woRl, bol, x, x, Cn, Cn);

        ln_kernel<<<BT, 256>>>(x, ln2g + l * Cn, ln2b + l * Cn, xn);
        gemm_mma<true, true ><<<gCF, 256, GEMM_SMEM_DYN>>>(xn, w1Rl, b1l, nullptr, h, Fn, Cn);
        gemm_mma<false, false><<<gCC, 256, GEMM_SMEM_DYN>>>(h,  w2Rl, b2l, x, x, Cn, Fn);
    }

    ln_kernel<<<BT, 256>>>(x, lnfg, lnfb, xn);
    gemm_mma<false, false><<<gCV, 256, GEMM_SMEM_DYN>>>(xn, wlmR, nullptr, nullptr, out, Vn, Cn);
}